// round 1
// baseline (speedup 1.0000x reference)
#include <cuda_runtime.h>

#define LW 512
#define LH 512
#define NIMG 12
#define RAD 8
#define HW 2048

// Scratch (device globals — no runtime allocation allowed)
__device__ float4 g_h4[(size_t)NIMG * LH * LW];   // horizontal window sums {sx, sy, sxy, sxx}
__device__ float  g_Ac[(size_t)NIMG * LH * LW];   // A at low-res
__device__ float  g_Bc[(size_t)NIMG * LH * LW];   // b at low-res

// ---------------------------------------------------------------------------
// Kernel 1: horizontal clamped box sums per row. One block per row (512 thr).
// ---------------------------------------------------------------------------
__global__ void hpass_kernel(const float* __restrict__ lrx,
                             const float* __restrict__ lry) {
    int row = blockIdx.x;                 // 0 .. NIMG*LH-1
    int t   = threadIdx.x;                // 0 .. 511
    __shared__ float sx[LW];
    __shared__ float sy[LW];
    size_t off = (size_t)row * LW + t;
    float xv = lrx[off];
    float yv = lry[off];
    sx[t] = xv;
    sy[t] = yv;
    __syncthreads();

    int lo = t - RAD; if (lo < 0) lo = 0;
    int hi = t + RAD; if (hi > LW - 1) hi = LW - 1;
    float ax = 0.f, ay = 0.f, axy = 0.f, axx = 0.f;
    for (int j = lo; j <= hi; ++j) {
        float a = sx[j], b = sy[j];
        ax  += a;
        ay  += b;
        axy += a * b;
        axx += a * a;
    }
    g_h4[off] = make_float4(ax, ay, axy, axx);
}

// ---------------------------------------------------------------------------
// Kernel 2: vertical clamped box sums via sliding window + A,b computation.
// Block = 128 columns x 64-row strip. 2 float4 loads per output.
// ---------------------------------------------------------------------------
#define VB_COLS 128
#define VB_ROWS 64

__global__ void vpass_kernel() {
    int img  = blockIdx.z;
    int col  = blockIdx.x * VB_COLS + threadIdx.x;
    int row0 = blockIdx.y * VB_ROWS;

    const float4* h = g_h4 + (size_t)img * LH * LW;

    float sx = 0.f, sy = 0.f, sxy = 0.f, sxx = 0.f;
    int lo = row0 - RAD; if (lo < 0) lo = 0;
    int hi = row0 + RAD; if (hi > LH - 1) hi = LH - 1;
    for (int rr = lo; rr <= hi; ++rr) {
        float4 v = h[(size_t)rr * LW + col];
        sx += v.x; sy += v.y; sxy += v.z; sxx += v.w;
    }

    int cl = col - RAD; if (cl < 0) cl = 0;
    int ch = col + RAD; if (ch > LW - 1) ch = LW - 1;
    float nxv = (float)(ch - cl + 1);

    size_t base = (size_t)img * LH * LW;
    for (int i = row0; i < row0 + VB_ROWS; ++i) {
        int rl = i - RAD; if (rl < 0) rl = 0;
        int rh = i + RAD; if (rh > LH - 1) rh = LH - 1;
        float nyv  = (float)(rh - rl + 1);
        float invN = 1.0f / (nxv * nyv);

        float mx  = sx  * invN;
        float my  = sy  * invN;
        float cov = sxy * invN - mx * my;
        float var = sxx * invN - mx * mx;
        float A   = cov / (var + 1e-8f);
        float Bv  = my - A * mx;

        size_t o = base + (size_t)i * LW + col;
        g_Ac[o] = A;
        g_Bc[o] = Bv;

        // slide window: i -> i+1
        int add = i + RAD + 1;
        if (add <= LH - 1) {
            float4 v = h[(size_t)add * LW + col];
            sx += v.x; sy += v.y; sxy += v.z; sxx += v.w;
        }
        int rem = i - RAD;
        if (rem >= 0) {
            float4 v = h[(size_t)rem * LW + col];
            sx -= v.x; sy -= v.y; sxy -= v.z; sxx -= v.w;
        }
    }
}

// ---------------------------------------------------------------------------
// Kernel 3: bilinear align-corners upsample of A,b fused with hr_x.
// One thread = 4 consecutive output pixels (float4 I/O on hr_x / out).
// ---------------------------------------------------------------------------
__global__ void upsample_kernel(const float* __restrict__ hrx,
                                float* __restrict__ out) {
    int idx  = blockIdx.x * blockDim.x + threadIdx.x;  // 12*2048*512 total
    int x4   = idx & 511;        // 2048/4 = 512 quads per row
    int rest = idx >> 9;
    int oy   = rest & 2047;
    int img  = rest >> 11;

    const float SC = 511.0f / 2047.0f;

    float yf = (float)oy * SC;
    int y0 = (int)yf; if (y0 > LH - 1) y0 = LH - 1;
    int y1 = y0 + 1;  if (y1 > LH - 1) y1 = LH - 1;
    float wy = yf - (float)y0;

    const float* Ap  = g_Ac + (size_t)img * LH * LW;
    const float* Bp  = g_Bc + (size_t)img * LH * LW;
    const float* Ar0 = Ap + (size_t)y0 * LW;
    const float* Ar1 = Ap + (size_t)y1 * LW;
    const float* Br0 = Bp + (size_t)y0 * LW;
    const float* Br1 = Bp + (size_t)y1 * LW;

    size_t hoff = ((size_t)img * HW + oy) * HW + (size_t)x4 * 4;
    float4 hr = *reinterpret_cast<const float4*>(hrx + hoff);
    float hv[4] = {hr.x, hr.y, hr.z, hr.w};
    float res[4];

#pragma unroll
    for (int k = 0; k < 4; ++k) {
        int ox = x4 * 4 + k;
        float xf = (float)ox * SC;
        int x0 = (int)xf; if (x0 > LW - 1) x0 = LW - 1;
        int x1 = x0 + 1;  if (x1 > LW - 1) x1 = LW - 1;
        float wx = xf - (float)x0;

        float a00 = __ldg(Ar0 + x0), a01 = __ldg(Ar0 + x1);
        float a10 = __ldg(Ar1 + x0), a11 = __ldg(Ar1 + x1);
        float b00 = __ldg(Br0 + x0), b01 = __ldg(Br0 + x1);
        float b10 = __ldg(Br1 + x0), b11 = __ldg(Br1 + x1);

        float at = a00 * (1.0f - wx) + a01 * wx;
        float ab = a10 * (1.0f - wx) + a11 * wx;
        float Av = at * (1.0f - wy) + ab * wy;

        float bt = b00 * (1.0f - wx) + b01 * wx;
        float bb = b10 * (1.0f - wx) + b11 * wx;
        float Bv = bt * (1.0f - wy) + bb * wy;

        res[k] = Av * hv[k] + Bv;
    }

    *reinterpret_cast<float4*>(out + hoff) =
        make_float4(res[0], res[1], res[2], res[3]);
}

// ---------------------------------------------------------------------------
extern "C" void kernel_launch(void* const* d_in, const int* in_sizes, int n_in,
                              void* d_out, int out_size) {
    const float* lrx = (const float*)d_in[0];
    const float* lry = (const float*)d_in[1];
    const float* hrx = (const float*)d_in[2];
    float* out = (float*)d_out;

    // Kernel 1: one block per low-res row
    hpass_kernel<<<NIMG * LH, LW>>>(lrx, lry);

    // Kernel 2: vertical sliding windows
    dim3 vgrid(LW / VB_COLS, LH / VB_ROWS, NIMG);
    vpass_kernel<<<vgrid, VB_COLS>>>();

    // Kernel 3: fused upsample
    long total_threads = (long)NIMG * HW * (HW / 4);   // 12,582,912
    int blocks = (int)(total_threads / 256);           // 49,152
    upsample_kernel<<<blocks, 256>>>(hrx, out);
}

// round 2
// speedup vs baseline: 1.1904x; 1.1904x over previous
#include <cuda_runtime.h>

#define LW 512
#define LH 512
#define NIMG 12
#define RAD 8
#define HW 2048

// Scratch (device globals — no runtime allocation allowed)
__device__ float4 g_h4[(size_t)NIMG * LH * LW];   // horizontal window sums {sx, sy, sxy, sxx}
__device__ float2 g_AB[(size_t)NIMG * LH * LW];   // {A, b} at low-res, interleaved

// ---------------------------------------------------------------------------
// Kernel 1: horizontal clamped box sums via block-wide prefix scan.
// One block per row (512 threads). window = P[hi] - P[lo-1].
// ---------------------------------------------------------------------------
__global__ void hpass_kernel(const float* __restrict__ lrx,
                             const float* __restrict__ lry) {
    int row = blockIdx.x;                 // 0 .. NIMG*LH-1
    int t   = threadIdx.x;                // 0 .. 511
    int lane = t & 31;
    int wid  = t >> 5;                    // 0..15

    __shared__ float4 sP[LW];
    __shared__ float4 wtot[16];

    size_t off = (size_t)row * LW + t;
    float xv = lrx[off];
    float yv = lry[off];

    float vx = xv, vy = yv, vxy = xv * yv, vxx = xv * xv;

    // warp-inclusive scan of 4 components
#pragma unroll
    for (int d = 1; d < 32; d <<= 1) {
        float tx  = __shfl_up_sync(0xffffffffu, vx,  d);
        float ty  = __shfl_up_sync(0xffffffffu, vy,  d);
        float txy = __shfl_up_sync(0xffffffffu, vxy, d);
        float txx = __shfl_up_sync(0xffffffffu, vxx, d);
        if (lane >= d) { vx += tx; vy += ty; vxy += txy; vxx += txx; }
    }
    if (lane == 31) wtot[wid] = make_float4(vx, vy, vxy, vxx);
    __syncthreads();

    // scan the 16 warp totals with warp 0
    if (wid == 0) {
        float4 w = (lane < 16) ? wtot[lane] : make_float4(0.f, 0.f, 0.f, 0.f);
        float ax = w.x, ay = w.y, az = w.z, aw = w.w;
#pragma unroll
        for (int d = 1; d < 16; d <<= 1) {
            float tx = __shfl_up_sync(0xffffffffu, ax, d);
            float ty = __shfl_up_sync(0xffffffffu, ay, d);
            float tz = __shfl_up_sync(0xffffffffu, az, d);
            float tw = __shfl_up_sync(0xffffffffu, aw, d);
            if (lane >= d) { ax += tx; ay += ty; az += tz; aw += tw; }
        }
        if (lane < 16) wtot[lane] = make_float4(ax, ay, az, aw);
    }
    __syncthreads();

    if (wid > 0) {
        float4 o = wtot[wid - 1];
        vx += o.x; vy += o.y; vxy += o.z; vxx += o.w;
    }
    sP[t] = make_float4(vx, vy, vxy, vxx);
    __syncthreads();

    int hi = t + RAD; if (hi > LW - 1) hi = LW - 1;
    int lo = t - RAD - 1;
    float4 ph = sP[hi];
    float4 res;
    if (lo >= 0) {
        float4 pl = sP[lo];
        res = make_float4(ph.x - pl.x, ph.y - pl.y, ph.z - pl.z, ph.w - pl.w);
    } else {
        res = ph;
    }
    g_h4[off] = res;
}

// ---------------------------------------------------------------------------
// Kernel 2: vertical clamped box sums via sliding window + A,b computation.
// ---------------------------------------------------------------------------
#define VB_COLS 128
#define VB_ROWS 64

__global__ void vpass_kernel() {
    int img  = blockIdx.z;
    int col  = blockIdx.x * VB_COLS + threadIdx.x;
    int row0 = blockIdx.y * VB_ROWS;

    const float4* h = g_h4 + (size_t)img * LH * LW;

    float sx = 0.f, sy = 0.f, sxy = 0.f, sxx = 0.f;
    int lo = row0 - RAD; if (lo < 0) lo = 0;
    int hi = row0 + RAD; if (hi > LH - 1) hi = LH - 1;
    for (int rr = lo; rr <= hi; ++rr) {
        float4 v = h[(size_t)rr * LW + col];
        sx += v.x; sy += v.y; sxy += v.z; sxx += v.w;
    }

    int cl = col - RAD; if (cl < 0) cl = 0;
    int ch = col + RAD; if (ch > LW - 1) ch = LW - 1;
    float nxv = (float)(ch - cl + 1);

    size_t base = (size_t)img * LH * LW;
    for (int i = row0; i < row0 + VB_ROWS; ++i) {
        int rl = i - RAD; if (rl < 0) rl = 0;
        int rh = i + RAD; if (rh > LH - 1) rh = LH - 1;
        float nyv  = (float)(rh - rl + 1);
        float invN = 1.0f / (nxv * nyv);

        float mx  = sx  * invN;
        float my  = sy  * invN;
        float cov = sxy * invN - mx * my;
        float var = sxx * invN - mx * mx;
        float A   = cov / (var + 1e-8f);
        float Bv  = my - A * mx;

        g_AB[base + (size_t)i * LW + col] = make_float2(A, Bv);

        // slide window: i -> i+1
        int add = i + RAD + 1;
        if (add <= LH - 1) {
            float4 v = h[(size_t)add * LW + col];
            sx += v.x; sy += v.y; sxy += v.z; sxx += v.w;
        }
        int rem = i - RAD;
        if (rem >= 0) {
            float4 v = h[(size_t)rem * LW + col];
            sx -= v.x; sy -= v.y; sxy -= v.z; sxx -= v.w;
        }
    }
}

// ---------------------------------------------------------------------------
// Kernel 3: fused bilinear upsample. One block = 1024-px segment of one
// output row. y-interp done once at low-res into shared; per-pixel work is
// 2 float2 LDS gathers + 4 FMA.
// ---------------------------------------------------------------------------
#define SEG 1024
#define UPTHREADS 256
#define SH_COLS 259

__global__ void upsample_kernel(const float* __restrict__ hrx,
                                float* __restrict__ out) {
    int bid = blockIdx.x;
    int seg = bid & 1;               // 0 or 1 (which 1024-px half)
    int oy  = (bid >> 1) & 2047;
    int img = bid >> 12;
    int t   = threadIdx.x;

    const float SC = 511.0f / 2047.0f;

    // y interpolation setup (uniform per block)
    float yf = (float)oy * SC;
    int y0 = (int)yf; if (y0 > LH - 1) y0 = LH - 1;
    int y1 = y0 + 1;  if (y1 > LH - 1) y1 = LH - 1;
    float wy = yf - (float)y0;

    // low-res x base for this segment: x0 of the segment's first pixel,
    // computed with the SAME expression as the per-pixel path (monotone).
    int ox_first = seg * SEG;
    int xbase = (int)((float)ox_first * SC);
    if (xbase > LW - 1) xbase = LW - 1;

    const float2* AB0 = g_AB + ((size_t)img * LH + y0) * LW;
    const float2* AB1 = g_AB + ((size_t)img * LH + y1) * LW;

    __shared__ float2 sAB[SH_COLS];   // y-interpolated {A,b} at low-res cols

    for (int i = t; i < SH_COLS; i += UPTHREADS) {
        int xc = xbase + i; if (xc > LW - 1) xc = LW - 1;
        float2 v0 = AB0[xc];
        float2 v1 = AB1[xc];
        sAB[i] = make_float2(v0.x + wy * (v1.x - v0.x),
                             v0.y + wy * (v1.y - v0.y));
    }
    __syncthreads();

    size_t hoff = ((size_t)img * HW + oy) * HW + (size_t)seg * SEG + (size_t)t * 4;
    float4 hr = *reinterpret_cast<const float4*>(hrx + hoff);
    float hv[4] = {hr.x, hr.y, hr.z, hr.w};
    float res[4];

#pragma unroll
    for (int k = 0; k < 4; ++k) {
        int ox = ox_first + t * 4 + k;
        float xf = (float)ox * SC;
        int x0 = (int)xf; if (x0 > LW - 1) x0 = LW - 1;
        int x1 = x0 + 1;  if (x1 > LW - 1) x1 = LW - 1;
        float wx = xf - (float)x0;

        float2 p = sAB[x0 - xbase];
        float2 q = sAB[x1 - xbase];
        float Av = p.x + wx * (q.x - p.x);
        float Bv = p.y + wx * (q.y - p.y);
        res[k] = Av * hv[k] + Bv;
    }

    *reinterpret_cast<float4*>(out + hoff) =
        make_float4(res[0], res[1], res[2], res[3]);
}

// ---------------------------------------------------------------------------
extern "C" void kernel_launch(void* const* d_in, const int* in_sizes, int n_in,
                              void* d_out, int out_size) {
    const float* lrx = (const float*)d_in[0];
    const float* lry = (const float*)d_in[1];
    const float* hrx = (const float*)d_in[2];
    float* out = (float*)d_out;

    hpass_kernel<<<NIMG * LH, LW>>>(lrx, lry);

    dim3 vgrid(LW / VB_COLS, LH / VB_ROWS, NIMG);
    vpass_kernel<<<vgrid, VB_COLS>>>();

    // 12 imgs * 2048 rows * 2 segments
    upsample_kernel<<<NIMG * HW * 2, UPTHREADS>>>(hrx, out);
}

// round 3
// speedup vs baseline: 1.1937x; 1.0028x over previous
#include <cuda_runtime.h>

#define LW 512
#define LH 512
#define NIMG 12
#define RAD 8
#define HW 2048

// Low-res {A, b} interleaved — only intermediate that touches HBM (24 MB).
__device__ float2 g_AB[(size_t)NIMG * LH * LW];

// ---------------------------------------------------------------------------
// Kernel 1 (fused stats): horizontal 17-tap sums kept in a shared-memory ring,
// vertical sliding-window sums in registers, emits A,b directly.
// Block = 128-column band x 64-row strip. Grid = 4 x 8 x 12.
// ---------------------------------------------------------------------------
#define BAND 128
#define STRIP 64

__global__ __launch_bounds__(BAND) void stats_kernel(const float* __restrict__ lrx,
                                                     const float* __restrict__ lry) {
    int img   = blockIdx.z;
    int cbase = blockIdx.x * BAND;
    int row0  = blockIdx.y * STRIP;
    int t     = threadIdx.x;            // 0..127
    int gc    = cbase + t;              // global column, always < 512
    int base  = cbase - RAD;            // raw-buffer origin (may be negative)

    __shared__ float2 raw[2][BAND + 2 * RAD];   // {x,y} of one input row (+halo)
    __shared__ float4 ring[2 * RAD + 1][BAND];  // 17-row ring of h-sums

    const float* xim = lrx + (size_t)img * LH * LW;
    const float* yim = lry + (size_t)img * LH * LW;

    int clo = gc - RAD; if (clo < 0) clo = 0;
    int chi = gc + RAD; if (chi > LW - 1) chi = LW - 1;
    float nx = (float)(chi - clo + 1);

    float sx = 0.f, sy = 0.f, sxy = 0.f, sxx = 0.f;
    int buf = 0;

    // ---- prologue: rows max(0,row0-8) .. row0+8 ----
    int r_lo = row0 - RAD; if (r_lo < 0) r_lo = 0;
    int r_hi = row0 + RAD;                       // row0 <= 448 -> r_hi <= 456
    for (int r = r_lo; r <= r_hi; ++r) {
        for (int i = t; i < BAND + 2 * RAD; i += BAND) {
            int g = base + i;
            float xv = 0.f, yv = 0.f;
            if (g >= 0 && g < LW) {
                xv = xim[(size_t)r * LW + g];
                yv = yim[(size_t)r * LW + g];
            }
            raw[buf][i] = make_float2(xv, yv);
        }
        __syncthreads();
        float ax = 0.f, ay = 0.f, axy = 0.f, axx = 0.f;
#pragma unroll
        for (int o = -RAD; o <= RAD; ++o) {
            int j = gc + o;
            if (j >= 0 && j < LW) {
                float2 v = raw[buf][t + RAD + o];
                ax += v.x; ay += v.y; axy += v.x * v.y; axx += v.x * v.x;
            }
        }
        ring[r % 17][t] = make_float4(ax, ay, axy, axx);
        sx += ax; sy += ay; sxy += axy; sxx += axx;
        buf ^= 1;
    }

    // ---- main loop: emit rows row0 .. row0+63 ----
    size_t abase = (size_t)img * LH * LW;
    for (int i = row0; i < row0 + STRIP; ++i) {
        int rl = i - RAD; if (rl < 0) rl = 0;
        int rh = i + RAD; if (rh > LH - 1) rh = LH - 1;
        float invN = 1.0f / (nx * (float)(rh - rl + 1));

        float mx  = sx  * invN;
        float my  = sy  * invN;
        float cov = sxy * invN - mx * my;
        float var = sxx * invN - mx * mx;
        float A   = cov / (var + 1e-8f);
        g_AB[abase + (size_t)i * LW + gc] = make_float2(A, my - A * mx);

        // subtract oldest row FIRST (its ring slot aliases the incoming row mod 17)
        int rem = i - RAD;
        if (rem >= 0) {
            float4 v = ring[rem % 17][t];
            sx -= v.x; sy -= v.y; sxy -= v.z; sxx -= v.w;
        }
        int add = i + RAD + 1;
        if (add <= LH - 1) {
            for (int ii = t; ii < BAND + 2 * RAD; ii += BAND) {
                int g = base + ii;
                float xv = 0.f, yv = 0.f;
                if (g >= 0 && g < LW) {
                    xv = xim[(size_t)add * LW + g];
                    yv = yim[(size_t)add * LW + g];
                }
                raw[buf][ii] = make_float2(xv, yv);
            }
            __syncthreads();
            float ax = 0.f, ay = 0.f, axy = 0.f, axx = 0.f;
#pragma unroll
            for (int o = -RAD; o <= RAD; ++o) {
                int j = gc + o;
                if (j >= 0 && j < LW) {
                    float2 v = raw[buf][t + RAD + o];
                    ax += v.x; ay += v.y; axy += v.x * v.y; axx += v.x * v.x;
                }
            }
            ring[add % 17][t] = make_float4(ax, ay, axy, axx);
            sx += ax; sy += ay; sxy += axy; sxx += axx;
            buf ^= 1;
        }
    }
}

// ---------------------------------------------------------------------------
// Kernel 2: fused bilinear upsample. One block = one full output row.
// 256 threads x 8 pixels (two float4 groups). Streaming ld/st hints keep
// L2 warm for the AB tables (fully L2-resident, 24 MB).
// ---------------------------------------------------------------------------
#define UPTHREADS 256

__global__ __launch_bounds__(UPTHREADS) void upsample_kernel(
        const float* __restrict__ hrx, float* __restrict__ out) {
    int bid = blockIdx.x;
    int oy  = bid & 2047;
    int img = bid >> 11;
    int t   = threadIdx.x;

    const float SC = 511.0f / 2047.0f;

    float yf = (float)oy * SC;
    int y0 = (int)yf; if (y0 > LH - 1) y0 = LH - 1;
    int y1 = y0 + 1;  if (y1 > LH - 1) y1 = LH - 1;
    float wy = yf - (float)y0;

    const float2* AB0 = g_AB + ((size_t)img * LH + y0) * LW;
    const float2* AB1 = g_AB + ((size_t)img * LH + y1) * LW;

    __shared__ float2 sAB[LW];   // y-interpolated {A,b} for the whole row

#pragma unroll
    for (int i = 0; i < 2; ++i) {
        int xc = t + i * UPTHREADS;
        float2 v0 = AB0[xc];
        float2 v1 = AB1[xc];
        sAB[xc] = make_float2(v0.x + wy * (v1.x - v0.x),
                              v0.y + wy * (v1.y - v0.y));
    }
    __syncthreads();

    size_t rowoff = ((size_t)img * HW + oy) * HW;

#pragma unroll
    for (int half = 0; half < 2; ++half) {
        int xq = half * 1024 + t * 4;           // first pixel of the float4
        size_t off = rowoff + xq;
        float4 hr = __ldcs(reinterpret_cast<const float4*>(hrx + off));
        float hv[4] = {hr.x, hr.y, hr.z, hr.w};
        float res[4];
#pragma unroll
        for (int k = 0; k < 4; ++k) {
            int ox = xq + k;
            float xf = (float)ox * SC;
            int x0 = (int)xf; if (x0 > LW - 1) x0 = LW - 1;
            int x1 = x0 + 1;  if (x1 > LW - 1) x1 = LW - 1;
            float wx = xf - (float)x0;
            float2 p = sAB[x0];
            float2 q = sAB[x1];
            float Av = p.x + wx * (q.x - p.x);
            float Bv = p.y + wx * (q.y - p.y);
            res[k] = Av * hv[k] + Bv;
        }
        __stcs(reinterpret_cast<float4*>(out + off),
               make_float4(res[0], res[1], res[2], res[3]));
    }
}

// ---------------------------------------------------------------------------
extern "C" void kernel_launch(void* const* d_in, const int* in_sizes, int n_in,
                              void* d_out, int out_size) {
    const float* lrx = (const float*)d_in[0];
    const float* lry = (const float*)d_in[1];
    const float* hrx = (const float*)d_in[2];
    float* out = (float*)d_out;

    dim3 sgrid(LW / BAND, LH / STRIP, NIMG);     // 4 x 8 x 12 = 384 blocks
    stats_kernel<<<sgrid, BAND>>>(lrx, lry);

    upsample_kernel<<<NIMG * HW, UPTHREADS>>>(hrx, out);   // 24576 blocks
}

// round 4
// speedup vs baseline: 1.7983x; 1.5065x over previous
#include <cuda_runtime.h>

#define LW 512
#define LH 512
#define NIMG 12
#define RAD 8
#define HW 2048

// Low-res {A, b} interleaved — only intermediate that touches HBM (24 MB).
__device__ float2 g_AB[(size_t)NIMG * LH * LW];

// ---------------------------------------------------------------------------
// Kernel 1 (fused stats), high-occupancy version.
// Tile = 64 out-cols x 16 out-rows. Grid = 8 x 32 x 12 = 3072 blocks, 128 thr.
// Phase 1: 80 threads (one per loaded col incl. +-8 halo) slide a vertical
//          17-row window; raw rows kept in a thread-private shared ring
//          (no syncs). Windowed column sums -> padded shared V tile.
// Phase 2: 128 threads (16 rows x 8 col-segments) slide horizontally over V,
//          emit A,b to shared, then one coalesced global write.
// ---------------------------------------------------------------------------
#define TC 64                 // out cols per tile
#define TR 16                 // out rows per tile
#define VC (TC + 2 * RAD)     // 80 loaded cols
#define VW 89                 // padded V row width (vpad(79)=88 -> 89)
#define STH 128

__device__ __forceinline__ int vpad(int v) { return v + (v >> 3); }

__global__ __launch_bounds__(STH) void stats_kernel(const float* __restrict__ lrx,
                                                    const float* __restrict__ lry) {
    __shared__ float4 Vsh[TR][VW];              // 22.8 KB vertical window sums
    __shared__ float2 ABsh[TR][TC];             // 8 KB
    __shared__ float2 ring[2 * RAD + 1][VC];    // 10.9 KB raw-row ring {x,y}

    int img = blockIdx.z;
    int cb  = blockIdx.x * TC;
    int r0  = blockIdx.y * TR;
    int t   = threadIdx.x;

    const float* xim = lrx + (size_t)img * LH * LW;
    const float* yim = lry + (size_t)img * LH * LW;

    // ---------------- phase 1: vertical sliding windows -------------------
    if (t < VC) {
        int gcol = cb - RAD + t;                // may be <0 or >=LW at edges
        bool cok = (gcol >= 0 && gcol < LW);
        float sx = 0.f, sy = 0.f, sxy = 0.f, sxx = 0.f;

        // init: rows r0-8 .. r0+8 (rows <0 contribute zero; r0+8 < LH always)
        for (int rr = r0 - RAD; rr <= r0 + RAD; ++rr) {
            float xv = 0.f, yv = 0.f;
            if (cok && rr >= 0) {
                xv = __ldg(xim + (size_t)rr * LW + gcol);
                yv = __ldg(yim + (size_t)rr * LW + gcol);
            }
            ring[(rr + 17) % 17][t] = make_float2(xv, yv);
            sx += xv; sy += yv; sxy += xv * yv; sxx += xv * xv;
        }

        for (int i = 0; i < TR; ++i) {
            Vsh[i][vpad(t)] = make_float4(sx, sy, sxy, sxx);

            int rsub = r0 + i - RAD;
            int radd = r0 + i + RAD + 1;        // radd - rsub = 17: same slot
            if (rsub >= 0) {
                float2 o = ring[(rsub + 17) % 17][t];  // read old FIRST
                sx -= o.x; sy -= o.y; sxy -= o.x * o.y; sxx -= o.x * o.x;
            }
            float xv = 0.f, yv = 0.f;
            if (cok && radd < LH) {
                xv = __ldg(xim + (size_t)radd * LW + gcol);
                yv = __ldg(yim + (size_t)radd * LW + gcol);
            }
            ring[radd % 17][t] = make_float2(xv, yv);
            sx += xv; sy += yv; sxy += xv * yv; sxx += xv * xv;
        }
    }
    __syncthreads();

    // ---------------- phase 2: horizontal sliding + A,b -------------------
    {
        int i   = t >> 3;          // row in tile, 0..15
        int seg = t & 7;           // 8-px segment, 0..7
        int c0  = seg * 8;
        int r   = r0 + i;

        int ylo = r - RAD; if (ylo < 0) ylo = 0;
        int yhi = r + RAD; if (yhi > LH - 1) yhi = LH - 1;
        float ny = (float)(yhi - ylo + 1);

        float sx = 0.f, sy = 0.f, sxy = 0.f, sxx = 0.f;
#pragma unroll
        for (int v = c0; v <= c0 + 2 * RAD; ++v) {
            float4 w = Vsh[i][vpad(v)];
            sx += w.x; sy += w.y; sxy += w.z; sxx += w.w;
        }
#pragma unroll
        for (int k = 0; k < 8; ++k) {
            int c  = c0 + k;
            int gc = cb + c;
            int xlo = gc - RAD; if (xlo < 0) xlo = 0;
            int xhi = gc + RAD; if (xhi > LW - 1) xhi = LW - 1;
            float invN = 1.0f / ((float)(xhi - xlo + 1) * ny);

            float mx  = sx  * invN;
            float my  = sy  * invN;
            float cov = sxy * invN - mx * my;
            float var = sxx * invN - mx * mx;
            float A   = cov / (var + 1e-8f);
            ABsh[i][c] = make_float2(A, my - A * mx);

            if (k < 7) {
                float4 a = Vsh[i][vpad(c + 2 * RAD + 1)];
                float4 s = Vsh[i][vpad(c)];
                sx += a.x - s.x; sy += a.y - s.y;
                sxy += a.z - s.z; sxx += a.w - s.w;
            }
        }
    }
    __syncthreads();

    // ---------------- coalesced output write ------------------------------
    size_t abase = (size_t)img * LH * LW;
    for (int idx = t; idx < TR * TC; idx += STH) {
        int i = idx >> 6;
        int c = idx & 63;
        g_AB[abase + (size_t)(r0 + i) * LW + cb + c] = ABsh[i][c];
    }
}

// ---------------------------------------------------------------------------
// Kernel 2: fused bilinear upsample (unchanged — 69.7us, 67% DRAM).
// ---------------------------------------------------------------------------
#define UPTHREADS 256

__global__ __launch_bounds__(UPTHREADS) void upsample_kernel(
        const float* __restrict__ hrx, float* __restrict__ out) {
    int bid = blockIdx.x;
    int oy  = bid & 2047;
    int img = bid >> 11;
    int t   = threadIdx.x;

    const float SC = 511.0f / 2047.0f;

    float yf = (float)oy * SC;
    int y0 = (int)yf; if (y0 > LH - 1) y0 = LH - 1;
    int y1 = y0 + 1;  if (y1 > LH - 1) y1 = LH - 1;
    float wy = yf - (float)y0;

    const float2* AB0 = g_AB + ((size_t)img * LH + y0) * LW;
    const float2* AB1 = g_AB + ((size_t)img * LH + y1) * LW;

    __shared__ float2 sAB[LW];   // y-interpolated {A,b} for the whole row

#pragma unroll
    for (int i = 0; i < 2; ++i) {
        int xc = t + i * UPTHREADS;
        float2 v0 = AB0[xc];
        float2 v1 = AB1[xc];
        sAB[xc] = make_float2(v0.x + wy * (v1.x - v0.x),
                              v0.y + wy * (v1.y - v0.y));
    }
    __syncthreads();

    size_t rowoff = ((size_t)img * HW + oy) * HW;

#pragma unroll
    for (int half = 0; half < 2; ++half) {
        int xq = half * 1024 + t * 4;
        size_t off = rowoff + xq;
        float4 hr = __ldcs(reinterpret_cast<const float4*>(hrx + off));
        float hv[4] = {hr.x, hr.y, hr.z, hr.w};
        float res[4];
#pragma unroll
        for (int k = 0; k < 4; ++k) {
            int ox = xq + k;
            float xf = (float)ox * SC;
            int x0 = (int)xf; if (x0 > LW - 1) x0 = LW - 1;
            int x1 = x0 + 1;  if (x1 > LW - 1) x1 = LW - 1;
            float wx = xf - (float)x0;
            float2 p = sAB[x0];
            float2 q = sAB[x1];
            float Av = p.x + wx * (q.x - p.x);
            float Bv = p.y + wx * (q.y - p.y);
            res[k] = Av * hv[k] + Bv;
        }
        __stcs(reinterpret_cast<float4*>(out + off),
               make_float4(res[0], res[1], res[2], res[3]));
    }
}

// ---------------------------------------------------------------------------
extern "C" void kernel_launch(void* const* d_in, const int* in_sizes, int n_in,
                              void* d_out, int out_size) {
    const float* lrx = (const float*)d_in[0];
    const float* lry = (const float*)d_in[1];
    const float* hrx = (const float*)d_in[2];
    float* out = (float*)d_out;

    dim3 sgrid(LW / TC, LH / TR, NIMG);      // 8 x 32 x 12 = 3072 blocks
    stats_kernel<<<sgrid, STH>>>(lrx, lry);

    upsample_kernel<<<NIMG * HW, UPTHREADS>>>(hrx, out);
}